// round 1
// baseline (speedup 1.0000x reference)
#include <cuda_runtime.h>

#define HH 128
#define WW 128
#define HWSZ (HH*WW)
#define CIN 64
#define COUT 128
#define NB 4
#define KTOT 576   // CIN * 9

// Scratch (device globals: no allocation allowed in kernel_launch)
__device__ float g_offmod[NB * 27 * HWSZ];   // [B][27][H*W]: ch 0..17 offsets (dy0,dx0,dy1,dx1,...), 18..26 modulators
__device__ float g_wt[KTOT * COUT];          // transposed weights: [k_gemm][oc], k_gemm = c*9 + k

// ---------------------------------------------------------------------------
// Kernel 0: transpose w_reg [Cout][Cin*9] -> g_wt [Cin*9][Cout]
// ---------------------------------------------------------------------------
__global__ void wt_kernel(const float* __restrict__ w_reg) {
    int i = blockIdx.x * 256 + threadIdx.x;
    if (i < KTOT * COUT) {
        int oc = i / KTOT;
        int k  = i - oc * KTOT;
        g_wt[k * COUT + oc] = w_reg[i];
    }
}

// ---------------------------------------------------------------------------
// Kernel A: fused offset + modulator 3x3 conv (27 output channels)
// Tile: 16 rows x 32 cols per block, 256 threads, 2 pixels/thread (y, y+8)
// ---------------------------------------------------------------------------
#define ATH 16
#define ATW 32
#define AHH 18
#define AHW 34
#define XT (CIN*AHH*AHW)   // 39168 floats

__global__ void __launch_bounds__(256, 1) offmod_kernel(
    const float* __restrict__ x,
    const float* __restrict__ w_off, const float* __restrict__ b_off,
    const float* __restrict__ w_mod, const float* __restrict__ b_mod)
{
    extern __shared__ float sm[];
    float* xs = sm;            // [CIN][18][34]
    float* ws = sm + XT;       // [CIN*9][28]  (27 outputs padded to 28 for float4)

    const int tid = threadIdx.x;
    const int b   = blockIdx.z;
    const int ty0 = blockIdx.y * ATH;
    const int tx0 = blockIdx.x * ATW;
    const float* xb = x + b * CIN * HWSZ;

    // Load x halo tile (zero-padded)
    for (int i = tid; i < XT; i += 256) {
        int c  = i / (AHH*AHW);
        int r  = i - c * (AHH*AHW);
        int yy = r / AHW;
        int xx = r - yy * AHW;
        int gy = ty0 + yy - 1;
        int gx = tx0 + xx - 1;
        float v = 0.f;
        if (gy >= 0 && gy < HH && gx >= 0 && gx < WW)
            v = xb[c * HWSZ + gy * WW + gx];
        xs[i] = v;
    }
    // Load all weights as ws[(c*9+k)][o], o in 0..26 (18 offset ch + 9 mod ch)
    for (int i = tid; i < CIN*9*27; i += 256) {
        int o  = i % 27;
        int ck = i / 27;
        int c  = ck / 9;
        int k  = ck - c * 9;
        float v = (o < 18) ? w_off[(o * CIN + c) * 9 + k]
                           : w_mod[((o - 18) * CIN + c) * 9 + k];
        ws[ck * 28 + o] = v;
    }
    __syncthreads();

    const int px = tid & 31;
    const int py = tid >> 5;   // 0..7, thread handles rows py and py+8

    float acc0[27], acc1[27];
    #pragma unroll
    for (int o = 0; o < 27; o++) { acc0[o] = 0.f; acc1[o] = 0.f; }

    for (int c = 0; c < CIN; c++) {
        const float* xc = xs + c * (AHH*AHW);
        #pragma unroll
        for (int ky = 0; ky < 3; ky++) {
            #pragma unroll
            for (int kx = 0; kx < 3; kx++) {
                float xv0 = xc[(py + ky) * AHW + px + kx];
                float xv1 = xc[(py + 8 + ky) * AHW + px + kx];
                const float4* wp = (const float4*)(ws + (c * 9 + ky * 3 + kx) * 28);
                #pragma unroll
                for (int q = 0; q < 7; q++) {
                    float4 t = wp[q];
                    const int o = 4 * q;
                    acc0[o+0] += t.x * xv0;  acc1[o+0] += t.x * xv1;
                    if (o + 1 < 27) { acc0[o+1] += t.y * xv0;  acc1[o+1] += t.y * xv1; }
                    if (o + 2 < 27) { acc0[o+2] += t.z * xv0;  acc1[o+2] += t.z * xv1; }
                    if (o + 3 < 27) { acc0[o+3] += t.w * xv0;  acc1[o+3] += t.w * xv1; }
                }
            }
        }
    }

    const int gy = ty0 + py;
    const int gx = tx0 + px;
    float* outp = g_offmod + b * 27 * HWSZ;
    #pragma unroll
    for (int o = 0; o < 27; o++) {
        float bias = (o < 18) ? b_off[o] : b_mod[o - 18];
        float v0 = acc0[o] + bias;
        float v1 = acc1[o] + bias;
        if (o >= 18) {
            v0 = 2.f / (1.f + __expf(-v0));
            v1 = 2.f / (1.f + __expf(-v1));
        }
        outp[o * HWSZ + gy * WW + gx]       = v0;
        outp[o * HWSZ + (gy + 8) * WW + gx] = v1;
    }
}

// ---------------------------------------------------------------------------
// Kernel B: bilinear sampling + 128x32x576 GEMM per 32-pixel row tile
// ---------------------------------------------------------------------------
#define BP  32   // pixels per block
#define SLK 36   // k-slice size for weight staging
#define NSL 16   // 576 / 36

__global__ void __launch_bounds__(256) dcn_kernel(const float* __restrict__ x,
                                                  float* __restrict__ out)
{
    extern __shared__ float sm[];
    float* S   = sm;                    // [576][32] sampled values
    float* Wsm = S + KTOT * BP;         // [36][128] weight slice
    float* cw  = Wsm + SLK * COUT;      // [4][288] bilinear corner weights (mask+validity folded)
    int*   ci  = (int*)(cw + 4 * 288);  // [4][288] clamped linear indices

    const int tid = threadIdx.x;
    const int b   = blockIdx.z;
    const int y   = blockIdx.y;
    const int x0  = blockIdx.x * BP;
    const float* offm = g_offmod + b * 27 * HWSZ;
    const float* xb   = x + b * CIN * HWSZ;

    // Phase 0: per (tap k, pixel p) bilinear coordinates
    for (int i = tid; i < 288; i += 256) {
        int k = i >> 5;
        int p = i & 31;
        int xx  = x0 + p;
        int lin = y * WW + xx;
        float dy = offm[(2*k)   * HWSZ + lin];
        float dx = offm[(2*k+1) * HWSZ + lin];
        float m  = offm[(18+k)  * HWSZ + lin];
        float pyf = (float)(y  + k / 3 - 1) + dy;
        float pxf = (float)(xx + k % 3 - 1) + dx;
        float fy = floorf(pyf);
        float fx = floorf(pxf);
        float tyf = pyf - fy;
        float txf = pxf - fx;
        int iy0 = (int)fy, ix0 = (int)fx;
        int iy1 = iy0 + 1, ix1 = ix0 + 1;
        float vy0 = (iy0 >= 0 && iy0 <= HH-1) ? 1.f : 0.f;
        float vy1 = (iy1 >= 0 && iy1 <= HH-1) ? 1.f : 0.f;
        float vx0 = (ix0 >= 0 && ix0 <= WW-1) ? 1.f : 0.f;
        float vx1 = (ix1 >= 0 && ix1 <= WW-1) ? 1.f : 0.f;
        int cy0 = min(max(iy0, 0), HH-1);
        int cy1 = min(max(iy1, 0), HH-1);
        int cx0 = min(max(ix0, 0), WW-1);
        int cx1 = min(max(ix1, 0), WW-1);
        cw[i      ] = (1.f - tyf) * (1.f - txf) * m * vy0 * vx0;
        cw[288 + i] = (1.f - tyf) * txf         * m * vy0 * vx1;
        cw[576 + i] = tyf * (1.f - txf)         * m * vy1 * vx0;
        cw[864 + i] = tyf * txf                 * m * vy1 * vx1;
        ci[i      ] = cy0 * WW + cx0;
        ci[288 + i] = cy0 * WW + cx1;
        ci[576 + i] = cy1 * WW + cx0;
        ci[864 + i] = cy1 * WW + cx1;
    }
    __syncthreads();

    // Phase 1: gather + bilinear blend into S[(c*9+k)][p]
    {
        const int p  = tid & 31;
        const int cg = tid >> 5;   // 0..7
        for (int k = 0; k < 9; k++) {
            int ii = (k << 5) + p;
            float w00 = cw[ii], w01 = cw[288 + ii], w10 = cw[576 + ii], w11 = cw[864 + ii];
            int   i00 = ci[ii], i01 = ci[288 + ii], i10 = ci[576 + ii], i11 = ci[864 + ii];
            #pragma unroll
            for (int cc = 0; cc < 8; cc++) {
                int c = cg * 8 + cc;
                const float* xc = xb + c * HWSZ;
                float v = w00 * xc[i00] + w01 * xc[i01] + w10 * xc[i10] + w11 * xc[i11];
                S[(c * 9 + k) * BP + p] = v;
            }
        }
    }

    // Phase 2: GEMM out[128][32] = Wt[576][128]^T-slice x S[576][32]
    const int pg  = tid & 7;    // pixel group: p = pg*4 .. pg*4+3
    const int ocg = tid >> 3;   // oc group: oc = ocg*4 .. ocg*4+3
    float acc[4][4];
    #pragma unroll
    for (int i = 0; i < 4; i++)
        #pragma unroll
        for (int j = 0; j < 4; j++) acc[i][j] = 0.f;

    for (int s = 0; s < NSL; s++) {
        const int k0 = s * SLK;
        __syncthreads();   // also serves as the post-sampling barrier at s=0
        for (int i = tid; i < SLK * COUT; i += 256)
            Wsm[i] = g_wt[k0 * COUT + i];
        __syncthreads();
        #pragma unroll
        for (int kk = 0; kk < SLK; kk++) {
            float4 w4 = *(const float4*)&Wsm[kk * COUT + ocg * 4];
            float4 s4 = *(const float4*)&S[(k0 + kk) * BP + pg * 4];
            acc[0][0] += w4.x * s4.x; acc[0][1] += w4.x * s4.y; acc[0][2] += w4.x * s4.z; acc[0][3] += w4.x * s4.w;
            acc[1][0] += w4.y * s4.x; acc[1][1] += w4.y * s4.y; acc[1][2] += w4.y * s4.z; acc[1][3] += w4.y * s4.w;
            acc[2][0] += w4.z * s4.x; acc[2][1] += w4.z * s4.y; acc[2][2] += w4.z * s4.z; acc[2][3] += w4.z * s4.w;
            acc[3][0] += w4.w * s4.x; acc[3][1] += w4.w * s4.y; acc[3][2] += w4.w * s4.z; acc[3][3] += w4.w * s4.w;
        }
    }

    float* ob = out + (b * COUT) * HWSZ + y * WW + x0 + pg * 4;
    #pragma unroll
    for (int i = 0; i < 4; i++) {
        int oc = ocg * 4 + i;
        float4 v = make_float4(acc[i][0], acc[i][1], acc[i][2], acc[i][3]);
        *(float4*)&ob[oc * HWSZ] = v;
    }
}

// ---------------------------------------------------------------------------
extern "C" void kernel_launch(void* const* d_in, const int* in_sizes, int n_in,
                              void* d_out, int out_size)
{
    const float* x     = (const float*)d_in[0];
    const float* w_off = (const float*)d_in[1];
    const float* b_off = (const float*)d_in[2];
    const float* w_mod = (const float*)d_in[3];
    const float* b_mod = (const float*)d_in[4];
    const float* w_reg = (const float*)d_in[5];
    float* out = (float*)d_out;
    (void)in_sizes; (void)n_in; (void)out_size;

    const int smA = (XT + CIN * 9 * 28) * 4;                       // 221184 B
    const int smB = (KTOT * BP + SLK * COUT + 4 * 288 * 2) * 4;    // 101376 B
    cudaFuncSetAttribute(offmod_kernel, cudaFuncAttributeMaxDynamicSharedMemorySize, smA);
    cudaFuncSetAttribute(dcn_kernel,    cudaFuncAttributeMaxDynamicSharedMemorySize, smB);

    wt_kernel<<<(KTOT * COUT + 255) / 256, 256>>>(w_reg);

    dim3 gA(WW / ATW, HH / ATH, NB);   // 4 x 8 x 4 = 128 blocks
    offmod_kernel<<<gA, 256, smA>>>(x, w_off, b_off, w_mod, b_mod);

    dim3 gB(WW / BP, HH, NB);          // 4 x 128 x 4 = 2048 blocks
    dcn_kernel<<<gB, 256, smB>>>(x, out);
}

// round 3
// speedup vs baseline: 1.2555x; 1.2555x over previous
#include <cuda_runtime.h>
#include <cuda_bf16.h>
#include <cstdint>

#define HH 128
#define WW 128
#define HWSZ (HH*WW)
#define CIN 64
#define COUT 128
#define NB 4
#define KTOT 576      // CIN * 9
#define NCHUNK 18     // K chunks of 32

// ---------------- device scratch ----------------
__device__ float g_offmod[NB * 27 * HWSZ];              // offsets(18) + modulators(9)
__device__ float g_xt[NB * HWSZ * CIN];                 // x transposed: [b][hw][c]
__device__ __nv_bfloat16 g_wh[NCHUNK * 128 * 32];       // W hi  [chunk][oc][kl]
__device__ __nv_bfloat16 g_wl[NCHUNK * 128 * 32];       // W lo

__device__ __forceinline__ uint32_t smem_u32(const void* p) {
    uint32_t a;
    asm("{ .reg .u64 t; cvta.to.shared.u64 t, %1; cvt.u32.u64 %0, t; }" : "=r"(a) : "l"(p));
    return a;
}

__device__ __forceinline__ void ldm4(uint32_t* r, uint32_t addr) {
    asm volatile("ldmatrix.sync.aligned.m8n8.x4.shared.b16 {%0,%1,%2,%3}, [%4];"
                 : "=r"(r[0]), "=r"(r[1]), "=r"(r[2]), "=r"(r[3]) : "r"(addr));
}
__device__ __forceinline__ void mma_bf16(float* c, const uint32_t* a, const uint32_t* b) {
    asm volatile("mma.sync.aligned.m16n8k16.row.col.f32.bf16.bf16.f32 "
                 "{%0,%1,%2,%3}, {%4,%5,%6,%7}, {%8,%9}, {%0,%1,%2,%3};"
                 : "+f"(c[0]), "+f"(c[1]), "+f"(c[2]), "+f"(c[3])
                 : "r"(a[0]), "r"(a[1]), "r"(a[2]), "r"(a[3]), "r"(b[0]), "r"(b[1]));
}
#define BARSYNC(id) asm volatile("bar.sync %0, 320;" :: "r"(id) : "memory")
#define BARARR(id)  asm volatile("bar.arrive %0, 320;" :: "r"(id) : "memory")
#define MEMBAR_CTA() asm volatile("membar.cta;" ::: "memory")

// ---------------------------------------------------------------------------
// x transpose: [b][c][hw] -> [b][hw][c]
// ---------------------------------------------------------------------------
__global__ void xt_kernel(const float* __restrict__ x) {
    __shared__ float sm[64][65];
    const int tid = threadIdx.x;
    const int b   = blockIdx.y;
    const int hw0 = blockIdx.x * 64;
    const float* xb = x + (size_t)b * CIN * HWSZ;
    #pragma unroll
    for (int it = 0; it < 16; it++) {
        int c   = (tid >> 6) + it * 4;
        int hwl = tid & 63;
        sm[hwl][c] = xb[c * HWSZ + hw0 + hwl];
    }
    __syncthreads();
    float* xtb = g_xt + ((size_t)b * HWSZ + hw0) * CIN;
    #pragma unroll
    for (int it = 0; it < 16; it++) {
        int hwl = (tid >> 6) + it * 4;
        int cl  = tid & 63;
        xtb[hwl * CIN + cl] = sm[hwl][cl];
    }
}

// ---------------------------------------------------------------------------
// W prep: split into bf16 hi/lo, K reordered as k_new = tap*64 + c
// ---------------------------------------------------------------------------
__global__ void wprep_kernel(const float* __restrict__ w_reg) {
    int i = blockIdx.x * 256 + threadIdx.x;
    if (i >= COUT * KTOT) return;
    int oc = i / KTOT;
    int kn = i - oc * KTOT;
    int tap = kn >> 6;
    int c   = kn & 63;
    float v = w_reg[oc * KTOT + c * 9 + tap];
    __nv_bfloat16 h = __float2bfloat16_rn(v);
    float lo = v - __bfloat162float(h);
    int chunk = kn >> 5;
    int kl    = kn & 31;
    g_wh[(chunk * 128 + oc) * 32 + kl] = h;
    g_wl[(chunk * 128 + oc) * 32 + kl] = __float2bfloat16_rn(lo);
}

// ---------------------------------------------------------------------------
// Kernel A: fused offset + modulator 3x3 conv (SIMT fp32, unchanged from R1)
// ---------------------------------------------------------------------------
#define ATH 16
#define ATW 32
#define AHH 18
#define AHW 34
#define XT (CIN*AHH*AHW)

__global__ void __launch_bounds__(256, 1) offmod_kernel(
    const float* __restrict__ x,
    const float* __restrict__ w_off, const float* __restrict__ b_off,
    const float* __restrict__ w_mod, const float* __restrict__ b_mod)
{
    extern __shared__ float sm[];
    float* xs = sm;
    float* ws = sm + XT;

    const int tid = threadIdx.x;
    const int b   = blockIdx.z;
    const int ty0 = blockIdx.y * ATH;
    const int tx0 = blockIdx.x * ATW;
    const float* xb = x + (size_t)b * CIN * HWSZ;

    for (int i = tid; i < XT; i += 256) {
        int c  = i / (AHH*AHW);
        int r  = i - c * (AHH*AHW);
        int yy = r / AHW;
        int xx = r - yy * AHW;
        int gy = ty0 + yy - 1;
        int gx = tx0 + xx - 1;
        float v = 0.f;
        if (gy >= 0 && gy < HH && gx >= 0 && gx < WW)
            v = xb[c * HWSZ + gy * WW + gx];
        xs[i] = v;
    }
    for (int i = tid; i < CIN*9*27; i += 256) {
        int o  = i % 27;
        int ck = i / 27;
        int c  = ck / 9;
        int k  = ck - c * 9;
        float v = (o < 18) ? w_off[(o * CIN + c) * 9 + k]
                           : w_mod[((o - 18) * CIN + c) * 9 + k];
        ws[ck * 28 + o] = v;
    }
    __syncthreads();

    const int px = tid & 31;
    const int py = tid >> 5;

    float acc0[27], acc1[27];
    #pragma unroll
    for (int o = 0; o < 27; o++) { acc0[o] = 0.f; acc1[o] = 0.f; }

    for (int c = 0; c < CIN; c++) {
        const float* xc = xs + c * (AHH*AHW);
        #pragma unroll
        for (int ky = 0; ky < 3; ky++) {
            #pragma unroll
            for (int kx = 0; kx < 3; kx++) {
                float xv0 = xc[(py + ky) * AHW + px + kx];
                float xv1 = xc[(py + 8 + ky) * AHW + px + kx];
                const float4* wp = (const float4*)(ws + (c * 9 + ky * 3 + kx) * 28);
                #pragma unroll
                for (int q = 0; q < 7; q++) {
                    float4 t = wp[q];
                    const int o = 4 * q;
                    acc0[o+0] += t.x * xv0;  acc1[o+0] += t.x * xv1;
                    if (o + 1 < 27) { acc0[o+1] += t.y * xv0;  acc1[o+1] += t.y * xv1; }
                    if (o + 2 < 27) { acc0[o+2] += t.z * xv0;  acc1[o+2] += t.z * xv1; }
                    if (o + 3 < 27) { acc0[o+3] += t.w * xv0;  acc1[o+3] += t.w * xv1; }
                }
            }
        }
    }

    const int gy = ty0 + py;
    const int gx = tx0 + px;
    float* outp = g_offmod + (size_t)b * 27 * HWSZ;
    #pragma unroll
    for (int o = 0; o < 27; o++) {
        float bias = (o < 18) ? b_off[o] : b_mod[o - 18];
        float v0 = acc0[o] + bias;
        float v1 = acc1[o] + bias;
        if (o >= 18) {
            v0 = 2.f / (1.f + __expf(-v0));
            v1 = 2.f / (1.f + __expf(-v1));
        }
        outp[o * HWSZ + gy * WW + gx]       = v0;
        outp[o * HWSZ + (gy + 8) * WW + gx] = v1;
    }
}

// ---------------------------------------------------------------------------
// Kernel B: warp-specialized bf16 mma.sync GEMM with bilinear sampling.
// Block = one (row y, batch b): D[128 oc][128 px], K = 576 in 18 chunks of 32.
// Warps 0-7 consume (mma), warps 8-9 produce (sample + W copy).
// Smem stage: Whi | Wlo | Shi | Slo, each 128 rows x 80B (32 bf16 + pad).
// ---------------------------------------------------------------------------
#define TBC 320
#define ROWB 80                 // smem row stride bytes (conflict-free for ldmatrix)
#define MATB (128 * ROWB)       // 10240
#define STAGEB (4 * MATB)       // 40960
#define SMEMB_TOTAL (2 * STAGEB)

#define BFULL0 1
#define BFULL1 2
#define BEMPTY0 3
#define BEMPTY1 4

__global__ void __launch_bounds__(TBC, 1) dcn_kernel(float* __restrict__ out)
{
    extern __shared__ char smb[];
    const uint32_t sb = smem_u32(smb);

    const int tid = threadIdx.x;
    const int wid = tid >> 5;
    const int lid = tid & 31;
    const int y   = blockIdx.x;
    const int b   = blockIdx.y;

    if (wid < 8) {
        // ---------------- consumers ----------------
        const int warp_m = wid & 3;       // oc tile of 32
        const int warp_n = wid >> 2;      // px tile of 64
        const int l = lid;
        const uint32_t aoffl = (uint32_t)((l & 15) * ROWB + (l >> 4) * 16);
        const uint32_t boffl = (uint32_t)(((l & 7) + ((l >> 4) ? 8 : 0)) * ROWB + ((l >> 3) & 1) * 16);

        float c[2][8][4];
        #pragma unroll
        for (int i = 0; i < 2; i++)
            #pragma unroll
            for (int j = 0; j < 8; j++)
                #pragma unroll
                for (int q = 0; q < 4; q++) c[i][j][q] = 0.f;

        for (int t = 0; t < NCHUNK; t++) {
            const int s = t & 1;
            BARSYNC(BFULL0 + s);
            const uint32_t stg = sb + (uint32_t)(s * STAGEB);
            #pragma unroll
            for (int ks = 0; ks < 2; ks++) {
                const uint32_t abase = stg + (uint32_t)(warp_m * 32 * ROWB + ks * 32) + aoffl;
                uint32_t ah[2][4], al[2][4];
                ldm4(ah[0], abase);
                ldm4(ah[1], abase + 16 * ROWB);
                ldm4(al[0], abase + MATB);
                ldm4(al[1], abase + MATB + 16 * ROWB);
                const uint32_t bbase = stg + (uint32_t)(2 * MATB + warp_n * 64 * ROWB + ks * 32) + boffl;
                uint32_t bh[8][2], bl[8][2];
                #pragma unroll
                for (int jj = 0; jj < 4; jj++) {
                    uint32_t tmp[4];
                    ldm4(tmp, bbase + (uint32_t)(jj * 16 * ROWB));
                    bh[2*jj][0] = tmp[0]; bh[2*jj][1] = tmp[1];
                    bh[2*jj+1][0] = tmp[2]; bh[2*jj+1][1] = tmp[3];
                    ldm4(tmp, bbase + (uint32_t)(MATB + jj * 16 * ROWB));
                    bl[2*jj][0] = tmp[0]; bl[2*jj][1] = tmp[1];
                    bl[2*jj+1][0] = tmp[2]; bl[2*jj+1][1] = tmp[3];
                }
                #pragma unroll
                for (int i = 0; i < 2; i++) {
                    #pragma unroll
                    for (int j = 0; j < 8; j++) {
                        mma_bf16(c[i][j], ah[i], bh[j]);
                        mma_bf16(c[i][j], ah[i], bl[j]);
                        mma_bf16(c[i][j], al[i], bh[j]);
                    }
                }
            }
            BARARR(BEMPTY0 + s);
        }

        // epilogue: fragment -> global (float2 stores)
        const int mrow = l >> 2;
        const int ncol = (l & 3) * 2;
        #pragma unroll
        for (int i = 0; i < 2; i++) {
            #pragma unroll
            for (int j = 0; j < 8; j++) {
                int m0 = warp_m * 32 + i * 16 + mrow;
                int n  = warp_n * 64 + j * 8 + ncol;
                float* p0 = out + ((size_t)(b * COUT + m0)) * HWSZ + y * WW + n;
                *(float2*)p0 = make_float2(c[i][j][0], c[i][j][1]);
                *(float2*)(p0 + 8 * HWSZ) = make_float2(c[i][j][2], c[i][j][3]);
            }
        }
    } else {
        // ---------------- producers ----------------
        const int tl = tid - 256;    // 0..63
        const float* offm = g_offmod + (size_t)b * 27 * HWSZ;
        const float* xtb  = g_xt + (size_t)b * HWSZ * CIN;

        for (int t = 0; t < NCHUNK; t++) {
            const int s = t & 1;
            if (t >= 2) BARSYNC(BEMPTY0 + s);
            char* stg = smb + s * STAGEB;

            // W hi/lo copy: 2 mats x 128 rows x 4 float4
            {
                const char* srcH = (const char*)g_wh + (size_t)t * 128 * 64;
                const char* srcL = (const char*)g_wl + (size_t)t * 128 * 64;
                #pragma unroll
                for (int it = 0; it < 16; it++) {
                    int i = tl + it * 64;      // 0..1023
                    int mat = i >> 9;
                    int rr  = (i >> 2) & 127;
                    int c4  = i & 3;
                    const char* src = (mat ? srcL : srcH) + rr * 64 + c4 * 16;
                    float4 v = *(const float4*)src;
                    *(float4*)(stg + mat * MATB + rr * ROWB + c4 * 16) = v;
                }
            }

            // Sampling: tap = t/2, channels cbase..cbase+31
            const int tap   = t >> 1;
            const int cbase = (t & 1) << 5;
            char* sh = stg + 2 * MATB;
            char* sl = stg + 3 * MATB;
            #pragma unroll
            for (int e = 0; e < 2; e++) {
                const int px  = tl * 2 + e;
                const int lin = y * WW + px;
                float dy = offm[(2*tap)   * HWSZ + lin];
                float dx = offm[(2*tap+1) * HWSZ + lin];
                float m  = offm[(18+tap)  * HWSZ + lin];
                float pyf = (float)(y  + tap / 3 - 1) + dy;
                float pxf = (float)(px + tap % 3 - 1) + dx;
                float fy = floorf(pyf);
                float fx = floorf(pxf);
                float ty = pyf - fy;
                float tx = pxf - fx;
                int iy0 = (int)fy, ix0 = (int)fx;
                int iy1 = iy0 + 1, ix1 = ix0 + 1;
                float vy0 = (iy0 >= 0 && iy0 <= HH-1) ? 1.f : 0.f;
                float vy1 = (iy1 >= 0 && iy1 <= HH-1) ? 1.f : 0.f;
                float vx0 = (ix0 >= 0 && ix0 <= WW-1) ? 1.f : 0.f;
                float vx1 = (ix1 >= 0 && ix1 <= WW-1) ? 1.f : 0.f;
                int cy0 = min(max(iy0, 0), HH-1);
                int cy1 = min(max(iy1, 0), HH-1);
                int cx0 = min(max(ix0, 0), WW-1);
                int cx1 = min(max(ix1, 0), WW-1);
                float w00 = (1.f - ty) * (1.f - tx) * m * vy0 * vx0;
                float w01 = (1.f - ty) * tx         * m * vy0 * vx1;
                float w10 = ty * (1.f - tx)         * m * vy1 * vx0;
                float w11 = ty * tx                 * m * vy1 * vx1;
                const float4* p00 = (const float4*)(xtb + (size_t)(cy0 * WW + cx0) * CIN + cbase);
                const float4* p01 = (const float4*)(xtb + (size_t)(cy0 * WW + cx1) * CIN + cbase);
                const float4* p10 = (const float4*)(xtb + (size_t)(cy1 * WW + cx0) * CIN + cbase);
                const float4* p11 = (const float4*)(xtb + (size_t)(cy1 * WW + cx1) * CIN + cbase);
                #pragma unroll
                for (int g = 0; g < 8; g++) {
                    float4 a = p00[g], bb = p01[g], cc = p10[g], d = p11[g];
                    float v0 = w00*a.x + w01*bb.x + w10*cc.x + w11*d.x;
                    float v1 = w00*a.y + w01*bb.y + w10*cc.y + w11*d.y;
                    float v2 = w00*a.z + w01*bb.z + w10*cc.z + w11*d.z;
                    float v3 = w00*a.w + w01*bb.w + w10*cc.w + w11*d.w;
                    __nv_bfloat16 h0 = __float2bfloat16_rn(v0);
                    __nv_bfloat16 h1 = __float2bfloat16_rn(v1);
                    __nv_bfloat16 h2 = __float2bfloat16_rn(v2);
                    __nv_bfloat16 h3 = __float2bfloat16_rn(v3);
                    __nv_bfloat16 l0 = __float2bfloat16_rn(v0 - __bfloat162float(h0));
                    __nv_bfloat16 l1 = __float2bfloat16_rn(v1 - __bfloat162float(h1));
                    __nv_bfloat16 l2 = __float2bfloat16_rn(v2 - __bfloat162float(h2));
                    __nv_bfloat16 l3 = __float2bfloat16_rn(v3 - __bfloat162float(h3));
                    uint32_t hp0 = (uint32_t)__bfloat16_as_ushort(h0) | ((uint32_t)__bfloat16_as_ushort(h1) << 16);
                    uint32_t hp1 = (uint32_t)__bfloat16_as_ushort(h2) | ((uint32_t)__bfloat16_as_ushort(h3) << 16);
                    uint32_t lp0 = (uint32_t)__bfloat16_as_ushort(l0) | ((uint32_t)__bfloat16_as_ushort(l1) << 16);
                    uint32_t lp1 = (uint32_t)__bfloat16_as_ushort(l2) | ((uint32_t)__bfloat16_as_ushort(l3) << 16);
                    *(uint2*)(sh + px * ROWB + g * 8) = make_uint2(hp0, hp1);
                    *(uint2*)(sl + px * ROWB + g * 8) = make_uint2(lp0, lp1);
                }
            }

            MEMBAR_CTA();
            BARARR(BFULL0 + s);
        }
    }
}

// ---------------------------------------------------------------------------
extern "C" void kernel_launch(void* const* d_in, const int* in_sizes, int n_in,
                              void* d_out, int out_size)
{
    const float* x     = (const float*)d_in[0];
    const float* w_off = (const float*)d_in[1];
    const float* b_off = (const float*)d_in[2];
    const float* w_mod = (const float*)d_in[3];
    const float* b_mod = (const float*)d_in[4];
    const float* w_reg = (const float*)d_in[5];
    float* out = (float*)d_out;
    (void)in_sizes; (void)n_in; (void)out_size;

    const int smA = (XT + CIN * 9 * 28) * 4;
    cudaFuncSetAttribute(offmod_kernel, cudaFuncAttributeMaxDynamicSharedMemorySize, smA);
    cudaFuncSetAttribute(dcn_kernel,    cudaFuncAttributeMaxDynamicSharedMemorySize, SMEMB_TOTAL);

    wprep_kernel<<<(COUT * KTOT + 255) / 256, 256>>>(w_reg);

    dim3 gT(HWSZ / 64, NB);
    xt_kernel<<<gT, 256>>>(x);

    dim3 gA(WW / ATW, HH / ATH, NB);
    offmod_kernel<<<gA, 256, smA>>>(x, w_off, b_off, w_mod, b_mod);

    dim3 gB(HH, NB);
    dcn_kernel<<<gB, TBC, SMEMB_TOTAL>>>(out);
}